// round 13
// baseline (speedup 1.0000x reference)
#include <cuda_runtime.h>

// Smoother: out = max(pred, (moving_sum_501(reflect_pad_T(pred)) + bias) / 501)
// pred: [B=8, T=16384, C=128] fp32, bias: [1] fp32, out: same shape.
//
// R12: paired-window stream sharing (L2-traffic cut).
// Evidence: R9-R11 flat at ~29-30us across occ 28-35% with ~10.5 TB/s of L2
// traffic => LTS-cap-bound. One warp runs TWO windows 256 rows apart with a
// 6-iteration lag:
//   lead(lower)(i) = x[t0+251+i] = M1(i-5)   (M1 = upper mid stream, reg ring)
//   trail(upper)(j)= x[t0+6+j]   = M0(i)     (M0 = lower mid stream, register)
// => 4 fresh streams per 2 outputs (M0, M1, TA, LB) instead of 6.
// Reads/output ~3.0 (was 3.84); LSU ops/output 3 (was 4). Stores use .cs.

#define Bn   8
#define Tn   16384
#define C4   32            // 128 channels / 4 per float4
#define Kn   501
#define Pn   250
#define SEG  32
#define NSEG (Tn / SEG)    // 512
#define TILE 32
#define NT   (Tn / TILE)   // 512
#define WPB  4             // warps per block
#define NPAIR (NSEG / 2)   // 256 window pairs per batch

// tile-sum scratch: 8 * 512 * 32 float4 = 2 MB
__device__ float4 g_TS[Bn * NT * C4];

__device__ __forceinline__ int refl(int k) {
    if (k < 0) k = -k;
    if (k >= Tn) k = 2 * Tn - 2 - k;
    return k;
}

__device__ __forceinline__ void acc4(float4& a, const float4 v) {
    a.x += v.x; a.y += v.y; a.z += v.z; a.w += v.w;
}
__device__ __forceinline__ void sub4(float4& a, const float4 v) {
    a.x -= v.x; a.y -= v.y; a.z -= v.z; a.w -= v.w;
}

// ---------------------------------------------------------------- kernel 1
__global__ void __launch_bounds__(128) tile_sum_kernel(
    const float4* __restrict__ pred)
{
    const int c = threadIdx.x & 31;
    const int w = threadIdx.x >> 5;
    const int j = blockIdx.x * WPB + w;      // tile 0..NT-1
    const int b = blockIdx.y;

    const float4* p = pred + ((size_t)b * Tn + (size_t)j * TILE) * C4 + c;

    float4 a0 = make_float4(0.f, 0.f, 0.f, 0.f);
    float4 a1 = make_float4(0.f, 0.f, 0.f, 0.f);
    float4 a2 = make_float4(0.f, 0.f, 0.f, 0.f);
    float4 a3 = make_float4(0.f, 0.f, 0.f, 0.f);

    #pragma unroll
    for (int base = 0; base < TILE; base += 8) {
        float4 r[8];
        #pragma unroll
        for (int u = 0; u < 8; u++) r[u] = p[(base + u) * C4];
        #pragma unroll
        for (int u = 0; u < 8; u += 4) {
            acc4(a0, r[u + 0]); acc4(a1, r[u + 1]);
            acc4(a2, r[u + 2]); acc4(a3, r[u + 3]);
        }
    }

    float4 s;
    s.x = (a0.x + a1.x) + (a2.x + a3.x);
    s.y = (a0.y + a1.y) + (a2.y + a3.y);
    s.z = (a0.z + a1.z) + (a2.z + a3.z);
    s.w = (a0.w + a1.w) + (a2.w + a3.w);

    g_TS[((size_t)b * NT + j) * C4 + c] = s;
}

// Sum rows [lo, hi) of column p (stride C4) using tile sums ts where possible.
__device__ __forceinline__ void range_sum(
    const float4* __restrict__ p, const float4* __restrict__ ts,
    int lo, int hi, float4& W)
{
    int jlo = (lo + TILE - 1) / TILE;
    int jhi = hi / TILE;
    if (jhi > jlo) {
        for (int r = lo; r < jlo * TILE; r++) acc4(W, p[r * C4]);
        #pragma unroll 4
        for (int j = jlo; j < jhi; j++)       acc4(W, ts[j * C4]);
        for (int r = jhi * TILE; r < hi; r++) acc4(W, p[r * C4]);
    } else {
        for (int r = lo; r < hi; r++) acc4(W, p[r * C4]);
    }
}

// Over-cover window init for window centered so it covers [t0_-250, t0_+250]:
// sum(tiles s_-8..s_+7)  [rows t0_-256 .. t0_+255]
//   - rows [t0_-256, t0_-251]  (6 surplus low)
//   - rows [t0_+251, t0_+255]  (5 surplus high)
// Requires 8 <= s_ <= NT-8 and rows in bounds.
__device__ __forceinline__ float4 win_init_fast(
    const float4* __restrict__ p, const float4* __restrict__ ts,
    int s_, int t0_)
{
    float4 a0 = make_float4(0.f, 0.f, 0.f, 0.f);
    float4 a1 = make_float4(0.f, 0.f, 0.f, 0.f);
    float4 a2 = make_float4(0.f, 0.f, 0.f, 0.f);
    float4 a3 = make_float4(0.f, 0.f, 0.f, 0.f);

    const float4* tq = ts + (s_ - 8) * C4;          // 16 tiles
    #pragma unroll
    for (int base = 0; base < 16; base += 8) {
        float4 r[8];
        #pragma unroll
        for (int u = 0; u < 8; u++) r[u] = tq[(base + u) * C4];
        #pragma unroll
        for (int u = 0; u < 8; u += 4) {
            acc4(a0, r[u + 0]); acc4(a1, r[u + 1]);
            acc4(a2, r[u + 2]); acc4(a3, r[u + 3]);
        }
    }
    const float4* qlo = p + (t0_ - 256) * C4;       // 6 rows
    const float4* qhi = p + (t0_ + Pn + 1) * C4;    // 5 rows
    {
        float4 e[6];
        #pragma unroll
        for (int u = 0; u < 6; u++) e[u] = qlo[u * C4];
        #pragma unroll
        for (int u = 0; u < 6; u++) {
            if      ((u & 3) == 0) sub4(a0, e[u]);
            else if ((u & 3) == 1) sub4(a1, e[u]);
            else if ((u & 3) == 2) sub4(a2, e[u]);
            else                   sub4(a3, e[u]);
        }
    }
    {
        float4 e[5];
        #pragma unroll
        for (int u = 0; u < 5; u++) e[u] = qhi[u * C4];
        #pragma unroll
        for (int u = 0; u < 5; u++) {
            if      ((u & 3) == 0) sub4(a0, e[u]);
            else if ((u & 3) == 1) sub4(a1, e[u]);
            else if ((u & 3) == 2) sub4(a2, e[u]);
            else                   sub4(a3, e[u]);
        }
    }
    float4 W;
    W.x = (a0.x + a1.x) + (a2.x + a3.x);
    W.y = (a0.y + a1.y) + (a2.y + a3.y);
    W.z = (a0.z + a1.z) + (a2.z + a3.z);
    W.w = (a0.w + a1.w) + (a2.w + a3.w);
    return W;
}

// Generic single-segment path (reflect-capable), used for boundary pairs.
__device__ __forceinline__ void slow_segment(
    const float4* __restrict__ p, float4* __restrict__ o,
    const float4* __restrict__ ts, int s, float bv, float inv)
{
    const int t0 = s * SEG;
    float4 W = make_float4(0.f, 0.f, 0.f, 0.f);
    int lo = t0 - Pn, hi = t0 + Pn + 1;
    if (lo < 0)  { range_sum(p, ts, 1, 1 - lo, W);               lo = 0;  }
    if (hi > Tn) { range_sum(p, ts, 2 * Tn - 1 - hi, Tn - 1, W); hi = Tn; }
    range_sum(p, ts, lo, hi, W);

    const float bi = bv * inv;
    for (int i = 0; i < SEG; i++) {
        int t = t0 + i;
        float4 L  = p[refl(t + Pn + 1) * C4];
        float4 Tt = p[refl(t - Pn) * C4];
        float4 M  = p[t * C4];
        float4 r;
        r.x = fmaxf(M.x, fmaf(W.x, inv, bi));
        r.y = fmaxf(M.y, fmaf(W.y, inv, bi));
        r.z = fmaxf(M.z, fmaf(W.z, inv, bi));
        r.w = fmaxf(M.w, fmaf(W.w, inv, bi));
        __stcs(&o[t * C4], r);
        W.x += L.x - Tt.x;
        W.y += L.y - Tt.y;
        W.z += L.z - Tt.z;
        W.w += L.w - Tt.w;
    }
}

// ---------------------------------------------------------------- kernel 2
__global__ void __launch_bounds__(128, 5) smoother_kernel(
    const float4* __restrict__ pred,
    const float*  __restrict__ bias,
    float4*       __restrict__ out)
{
    const int c  = threadIdx.x & 31;        // float4 lane
    const int w  = threadIdx.x >> 5;        // warp in block
    const int pi = blockIdx.x * WPB + w;    // pair index 0..NPAIR-1
    const int b  = blockIdx.y;

    // pair (s, s+8): s ranges over {16q + r : r<8} = all "first" segments
    const int q_ = pi >> 3;
    const int r_ = pi & 7;
    const int s  = q_ * 16 + r_;
    const int t0 = s * SEG;
    const int tB = t0 + 256;                // upper window base (segment s+8)

    const float4* p  = pred + (size_t)b * Tn * C4 + c;
    float4*       o  = out  + (size_t)b * Tn * C4 + c;
    const float4* ts = g_TS + (size_t)b * NT * C4 + c;

    const float bv  = bias[0];
    const float inv = 1.0f / (float)Kn;
    const float bi  = bv * inv;

    // Fast iff: tiles s-8..s+15 valid (8 <= s, s+15 <= 511) and max row
    // touched t0+538 <= Tn-1  =>  8 <= s <= 495.
    const bool fast = (s >= 8) && (s <= 495);

    if (fast) {
        // M1h[pp] = x[tB + pp - 5]   (pp = 0..36). Prologue pp=0..4.
        float4 M1h[37];
        {
            const float4* pr = p + (tB - 5) * C4;   // = t0+251 .. t0+255
            #pragma unroll
            for (int pp = 0; pp < 5; pp++) M1h[pp] = pr[pp * C4];
        }

        float4 WA = win_init_fast(p, ts, s,     t0);   // win(t0)
        float4 WB = win_init_fast(p, ts, s + 8, tB);   // win(tB)

        const float4* pm0 = p + t0 * C4;          // M0 stream
        const float4* pm1 = p + tB * C4;          // M1 stream
        const float4* pta = p + (t0 - Pn) * C4;   // TA stream
        const float4* plb = p + (t0 + 501) * C4;  // LB stream
        float4*       oa  = o + t0 * C4;
        float4*       ob  = o + tB * C4;

        #pragma unroll
        for (int i = 0; i < 38; i++) {
            float4 M0, TAv, LBv;
            if (i <= 36)           M0  = pm0[i * C4];
            if (i <  32)           M1h[i + 5] = pm1[i * C4];
            if (i <= 30)           TAv = pta[i * C4];
            if (i >= 6 && i <= 36) LBv = plb[i * C4];

            if (i < 32) {
                float4 r;
                r.x = fmaxf(M0.x, fmaf(WA.x, inv, bi));
                r.y = fmaxf(M0.y, fmaf(WA.y, inv, bi));
                r.z = fmaxf(M0.z, fmaf(WA.z, inv, bi));
                r.w = fmaxf(M0.w, fmaf(WA.w, inv, bi));
                __stcs(&oa[i * C4], r);
                if (i <= 30) {
                    // lead_A(i) = x[t0+251+i] = M1(i-5) = M1h[i]
                    WA.x += M1h[i].x - TAv.x;
                    WA.y += M1h[i].y - TAv.y;
                    WA.z += M1h[i].z - TAv.z;
                    WA.w += M1h[i].w - TAv.w;
                }
            }
            if (i >= 6) {
                // j = i-6; mid_B(j) = M1(j) = M1h[i-1]
                float4 mB = M1h[i - 1];
                float4 r;
                r.x = fmaxf(mB.x, fmaf(WB.x, inv, bi));
                r.y = fmaxf(mB.y, fmaf(WB.y, inv, bi));
                r.z = fmaxf(mB.z, fmaf(WB.z, inv, bi));
                r.w = fmaxf(mB.w, fmaf(WB.w, inv, bi));
                __stcs(&ob[(i - 6) * C4], r);
                if (i <= 36) {
                    // lead_B(j) = x[t0+507+j] = LBv; trail_B(j) = x[t0+i] = M0
                    WB.x += LBv.x - M0.x;
                    WB.y += LBv.y - M0.y;
                    WB.z += LBv.z - M0.z;
                    WB.w += LBv.w - M0.w;
                }
            }
        }
    } else {
        slow_segment(p, o, ts, s,     bv, inv);
        slow_segment(p, o, ts, s + 8, bv, inv);
    }
}

extern "C" void kernel_launch(void* const* d_in, const int* in_sizes, int n_in,
                              void* d_out, int out_size)
{
    const float4* pred = (const float4*)d_in[0];
    const float*  bias = (const float*)d_in[1];
    float4*       out  = (float4*)d_out;

    (void)in_sizes; (void)n_in; (void)out_size;

    dim3 g1(NT / WPB, Bn);       // 128 x 8 blocks, 4 tiles each
    dim3 g2(NPAIR / WPB, Bn);    // 64 x 8 blocks, 4 window-pairs each
    dim3 blk(32 * WPB);          // 128 threads
    tile_sum_kernel<<<g1, blk>>>(pred);
    smoother_kernel<<<g2, blk>>>(pred, bias, out);
}